// round 7
// baseline (speedup 1.0000x reference)
#include <cuda_runtime.h>
#include <cuda_bf16.h>
#include <cstdint>
#include <math.h>

// Problem constants
#define Bz 4
#define Sz 2048
#define Dz 2048
#define NHz 16
#define DHz 128

#define TOT (4UL*2048UL*2048UL)   // B*S*D elements

// Scratch (allocation-free rule: __device__ globals)
__device__ float g_Q[TOT];
__device__ float g_K[TOT];
__device__ float g_V[TOT];
__device__ float g_A[TOT];
__device__ float g_R[TOT];
__device__ __nv_bfloat16 g_inhi[TOT];
__device__ __nv_bfloat16 g_inlo[TOT];
__device__ __nv_bfloat16 g_wthi[2048UL*2048UL];  // transposed weight hi (N x K)
__device__ __nv_bfloat16 g_wtlo[2048UL*2048UL];  // transposed weight lo (N x K)

// ===========================================================================
// mma.sync helpers (baseline PTX, works on plain compute_103 target)
// ===========================================================================
__device__ __forceinline__ void mma16816(float* c, const uint32_t* a, const uint32_t* b) {
    asm volatile(
        "mma.sync.aligned.m16n8k16.row.col.f32.bf16.bf16.f32 "
        "{%0,%1,%2,%3}, {%4,%5,%6,%7}, {%8,%9}, {%0,%1,%2,%3};"
        : "+f"(c[0]), "+f"(c[1]), "+f"(c[2]), "+f"(c[3])
        : "r"(a[0]), "r"(a[1]), "r"(a[2]), "r"(a[3]), "r"(b[0]), "r"(b[1]));
}

__device__ __forceinline__ void cp_async16(void* dst, const void* src) {
    uint32_t d;
    asm("{ .reg .u64 t; cvta.to.shared.u64 t, %1; cvt.u32.u64 %0, t; }"
        : "=r"(d) : "l"(dst));
    asm volatile("cp.async.cg.shared.global [%0], [%1], 16;" :: "r"(d), "l"(src));
}
__device__ __forceinline__ void cp_commit() {
    asm volatile("cp.async.commit_group;");
}
template<int N> __device__ __forceinline__ void cp_wait() {
    asm volatile("cp.async.wait_group %0;" :: "n"(N));
}

// ===========================================================================
// Tensor-core split-bf16 GEMM: C[M,2048] = A @ Bt^T (+Res)
//   3 passes: Ahi*Bhi + Ahi*Blo + Alo*Bhi   (lo*lo dropped; err ~ eps^2)
// A: (M x 2048) bf16 row-major (K contiguous).
// Bt: (2048 x 2048) bf16 = W^T, row = N index, K contiguous.
// CTA: 128x128 tile, 8 warps (2x4), warp tile 64x32. K-chunk 32, 2-stage cp.async.
// ===========================================================================
#define KC 32
#define STB 40                         // smem row stride in bf16 (80 bytes)
#define TILE_BYTES (128 * STB * 2)     // 10240 per operand tile
#define STAGE_BYTES (2 * TILE_BYTES)   // A + B
#define CH_TOT 192                     // 3 passes * 64 chunks

__global__ __launch_bounds__(256, 2) void wgemm(
    const __nv_bfloat16* __restrict__ Ahi, const __nv_bfloat16* __restrict__ Alo,
    const __nv_bfloat16* __restrict__ Bhi, const __nv_bfloat16* __restrict__ Blo,
    const float* __restrict__ Res, float* __restrict__ C)
{
    __shared__ char smem[2 * STAGE_BYTES];   // 40 KB

    const int tid = threadIdx.x;
    const int lane = tid & 31, wid = tid >> 5;
    const int wm = wid >> 2, wn = wid & 3;       // warp grid 2x4
    const int g = lane >> 2, tig = lane & 3;     // mma groupID / threadID-in-group
    const int m0 = blockIdx.y * 128, n0 = blockIdx.x * 128;

    float acc[4][4][4];
#pragma unroll
    for (int m = 0; m < 4; m++)
#pragma unroll
        for (int n = 0; n < 4; n++)
#pragma unroll
            for (int e = 0; e < 4; e++) acc[m][n][e] = 0.f;

    auto load_chunk = [&](int c, int st) {
        const int pass = c >> 6;
        const int k0 = (c & 63) * KC;
        const __nv_bfloat16* Ag = (pass == 2 ? Alo : Ahi) + (long)m0 * 2048 + k0;
        const __nv_bfloat16* Bg = (pass == 1 ? Blo : Bhi) + (long)n0 * 2048 + k0;
        char* As = smem + st * STAGE_BYTES;
        char* Bs = As + TILE_BYTES;
        // 512 16B-chunks per tile; 2 per thread per tile
#pragma unroll
        for (int i = 0; i < 2; i++) {
            int idx = i * 256 + tid;
            int r = idx >> 2, kc = idx & 3;
            cp_async16(As + r * (STB * 2) + kc * 16, Ag + (long)r * 2048 + kc * 8);
            cp_async16(Bs + r * (STB * 2) + kc * 16, Bg + (long)r * 2048 + kc * 8);
        }
        cp_commit();
    };

    load_chunk(0, 0);

    for (int c = 0; c < CH_TOT; c++) {
        const int st = c & 1;
        if (c + 1 < CH_TOT) {
            load_chunk(c + 1, (c + 1) & 1);
            cp_wait<1>();
        } else {
            cp_wait<0>();
        }
        __syncthreads();

        const char* As = smem + st * STAGE_BYTES;
        const char* Bs = As + TILE_BYTES;
#pragma unroll
        for (int kk = 0; kk < KC; kk += 16) {
            uint32_t a[4][4], b[4][2];
#pragma unroll
            for (int m = 0; m < 4; m++) {
                int r = wm * 64 + m * 16 + g;
                const char* base = As + r * (STB * 2) + (kk + tig * 2) * 2;
                a[m][0] = *(const uint32_t*)base;
                a[m][1] = *(const uint32_t*)(base + 8 * (STB * 2));
                a[m][2] = *(const uint32_t*)(base + 16);
                a[m][3] = *(const uint32_t*)(base + 8 * (STB * 2) + 16);
            }
#pragma unroll
            for (int n = 0; n < 4; n++) {
                int r = wn * 32 + n * 8 + g;
                const char* base = Bs + r * (STB * 2) + (kk + tig * 2) * 2;
                b[n][0] = *(const uint32_t*)base;
                b[n][1] = *(const uint32_t*)(base + 16);
            }
#pragma unroll
            for (int m = 0; m < 4; m++)
#pragma unroll
                for (int n = 0; n < 4; n++)
                    mma16816(acc[m][n], a[m], b[n]);
        }
        __syncthreads();
    }

    // Epilogue: direct float2 stores (+ optional residual)
#pragma unroll
    for (int m = 0; m < 4; m++) {
        int row0 = m0 + wm * 64 + m * 16 + g;
#pragma unroll
        for (int n = 0; n < 4; n++) {
            int col = n0 + wn * 32 + n * 8 + tig * 2;
            long o0 = (long)row0 * 2048 + col;
            long o1 = (long)(row0 + 8) * 2048 + col;
            float2 v0 = { acc[m][n][0], acc[m][n][1] };
            float2 v1 = { acc[m][n][2], acc[m][n][3] };
            if (Res) {
                float2 r0 = *(const float2*)&Res[o0];
                float2 r1 = *(const float2*)&Res[o1];
                v0.x += r0.x; v0.y += r0.y;
                v1.x += r1.x; v1.y += r1.y;
            }
            *(float2*)&C[o0] = v0;
            *(float2*)&C[o1] = v1;
        }
    }
}

// ===========================================================================
// fp32 -> (hi, lo) bf16 split, vectorized
// ===========================================================================
__global__ void split_f32(const float4* __restrict__ X,
                          __nv_bfloat16* __restrict__ hi,
                          __nv_bfloat16* __restrict__ lo)
{
    long i = (long)blockIdx.x * blockDim.x + threadIdx.x;
    float4 v = X[i];
    __nv_bfloat16 h0 = __float2bfloat16(v.x), h1 = __float2bfloat16(v.y);
    __nv_bfloat16 h2 = __float2bfloat16(v.z), h3 = __float2bfloat16(v.w);
    __nv_bfloat16 l0 = __float2bfloat16(v.x - __bfloat162float(h0));
    __nv_bfloat16 l1 = __float2bfloat16(v.y - __bfloat162float(h1));
    __nv_bfloat16 l2 = __float2bfloat16(v.z - __bfloat162float(h2));
    __nv_bfloat16 l3 = __float2bfloat16(v.w - __bfloat162float(h3));
    __nv_bfloat162* hp = (__nv_bfloat162*)hi;
    __nv_bfloat162* lp = (__nv_bfloat162*)lo;
    hp[2 * i]     = __nv_bfloat162(h0, h1);
    hp[2 * i + 1] = __nv_bfloat162(h2, h3);
    lp[2 * i]     = __nv_bfloat162(l0, l1);
    lp[2 * i + 1] = __nv_bfloat162(l2, l3);
}

// ===========================================================================
// Weight split + transpose: W (K x N) fp32 -> hiT, loT (N x K) bf16
// ===========================================================================
__global__ void split_wT(const float* __restrict__ W,
                         __nv_bfloat16* __restrict__ hiT,
                         __nv_bfloat16* __restrict__ loT)
{
    __shared__ float t[32][33];
    int n0 = blockIdx.x * 32, k0 = blockIdx.y * 32;
    int tx = threadIdx.x, ty = threadIdx.y;   // (32, 8)
#pragma unroll
    for (int j = 0; j < 4; j++)
        t[ty + 8 * j][tx] = W[(long)(k0 + ty + 8 * j) * 2048 + n0 + tx];
    __syncthreads();
#pragma unroll
    for (int j = 0; j < 4; j++) {
        int r = ty + 8 * j;                    // N offset within block
        float x = t[tx][r];                    // = W[k0+tx][n0+r]
        __nv_bfloat16 h = __float2bfloat16(x);
        __nv_bfloat16 l = __float2bfloat16(x - __bfloat162float(h));
        long o = (long)(n0 + r) * 2048 + k0 + tx;
        hiT[o] = h;
        loT[o] = l;
    }
}

// ---------------------------------------------------------------------------
// RoPE: in-place on (B,S,NH*128) with interleaved pairs per head
// ---------------------------------------------------------------------------
__global__ void rope_kernel(float* __restrict__ X,
                            const float* __restrict__ cosb,
                            const float* __restrict__ sinb)
{
    int idx = blockIdx.x * blockDim.x + threadIdx.x;
    int i = idx & 63;
    int h = (idx >> 6) & 15;
    int s = (idx >> 10) & 2047;
    int b = idx >> 21;
    long base = ((long)(b * Sz + s)) * Dz + h * DHz + 2 * i;
    float c = cosb[s * 64 + i], sn = sinb[s * 64 + i];
    float x1 = X[base], x2 = X[base + 1];
    X[base]     = x1 * c - x2 * sn;
    X[base + 1] = x1 * sn + x2 * c;
}

// ---------------------------------------------------------------------------
// Flash attention (fp32 SIMT), mask int32 nonzero == masked
// ---------------------------------------------------------------------------
#define FL_SMEM ((64*128 + 64*129 + 64*128 + 64*64) * 4)

__global__ __launch_bounds__(256) void flash_kernel(
    const float* __restrict__ Q, const float* __restrict__ K,
    const float* __restrict__ V, const int* __restrict__ mask,
    float* __restrict__ O)
{
    extern __shared__ float sm[];
    float* sQ = sm;
    float* sK = sQ + 64 * 128;
    float* sV = sK + 64 * 129;
    float* sS = sV + 64 * 128;

    const int tid = threadIdx.x;
    const int tx = tid & 15, ty = tid >> 4;
    const int blk = blockIdx.x;
    const int qt = blk & 31;
    const int h  = (blk >> 5) & 15;
    const int b  = blk >> 9;
    const int q0 = qt * 64;
    const float scale = 0.08838834764831845f;

#pragma unroll
    for (int r = 0; r < 32; r++) {
        int e = r * 256 + tid;
        int row = e >> 7, col = e & 127;
        sQ[row * 128 + col] = Q[((long)(b * Sz + q0 + row)) * Dz + h * DHz + col];
    }

    float m_i[4], l_i[4], o[4][8];
#pragma unroll
    for (int i = 0; i < 4; i++) {
        m_i[i] = -1e30f; l_i[i] = 0.f;
#pragma unroll
        for (int c = 0; c < 8; c++) o[i][c] = 0.f;
    }

    const int* mrow = mask + (long)b * Sz;

    for (int k0 = 0; k0 < Sz; k0 += 64) {
        __syncthreads();
#pragma unroll
        for (int r = 0; r < 32; r++) {
            int e = r * 256 + tid;
            int row = e >> 7, col = e & 127;
            long gg = ((long)(b * Sz + k0 + row)) * Dz + h * DHz + col;
            sK[row * 129 + col] = K[gg];
            sV[row * 128 + col] = V[gg];
        }
        __syncthreads();

        float accs[4][4];
#pragma unroll
        for (int i = 0; i < 4; i++)
#pragma unroll
            for (int j = 0; j < 4; j++) accs[i][j] = 0.f;

#pragma unroll 4
        for (int k = 0; k < 128; k++) {
            float a[4], bb[4];
#pragma unroll
            for (int i = 0; i < 4; i++) a[i]  = sQ[(ty * 4 + i) * 128 + k];
#pragma unroll
            for (int j = 0; j < 4; j++) bb[j] = sK[(tx * 4 + j) * 129 + k];
#pragma unroll
            for (int i = 0; i < 4; i++)
#pragma unroll
                for (int j = 0; j < 4; j++) accs[i][j] += a[i] * bb[j];
        }

        float sv[4][4];
#pragma unroll
        for (int j = 0; j < 4; j++) {
            bool msk = mrow[k0 + tx * 4 + j] != 0;
#pragma unroll
            for (int i = 0; i < 4; i++)
                sv[i][j] = msk ? -1e30f : accs[i][j] * scale;
        }

#pragma unroll
        for (int i = 0; i < 4; i++) {
            float tm = fmaxf(fmaxf(sv[i][0], sv[i][1]), fmaxf(sv[i][2], sv[i][3]));
#pragma unroll
            for (int d = 1; d < 16; d <<= 1)
                tm = fmaxf(tm, __shfl_xor_sync(0xffffffffu, tm, d));
            float nm = fmaxf(m_i[i], tm);
            float corr = __expf(m_i[i] - nm);
            float p[4], ps = 0.f;
#pragma unroll
            for (int j = 0; j < 4; j++) { p[j] = __expf(sv[i][j] - nm); ps += p[j]; }
#pragma unroll
            for (int d = 1; d < 16; d <<= 1)
                ps += __shfl_xor_sync(0xffffffffu, ps, d);
            l_i[i] = l_i[i] * corr + ps;
            m_i[i] = nm;
#pragma unroll
            for (int c = 0; c < 8; c++) o[i][c] *= corr;
#pragma unroll
            for (int j = 0; j < 4; j++)
                sS[(ty * 4 + i) * 64 + tx * 4 + j] = p[j];
        }
        __syncthreads();

#pragma unroll 4
        for (int kc = 0; kc < 64; kc++) {
            float4 v0 = *(const float4*)&sV[kc * 128 + tx * 8];
            float4 v1 = *(const float4*)&sV[kc * 128 + tx * 8 + 4];
#pragma unroll
            for (int i = 0; i < 4; i++) {
                float s = sS[(ty * 4 + i) * 64 + kc];
                o[i][0] += s * v0.x; o[i][1] += s * v0.y;
                o[i][2] += s * v0.z; o[i][3] += s * v0.w;
                o[i][4] += s * v1.x; o[i][5] += s * v1.y;
                o[i][6] += s * v1.z; o[i][7] += s * v1.w;
            }
        }
    }

#pragma unroll
    for (int i = 0; i < 4; i++) {
        float inv = 1.f / l_i[i];
        long base = ((long)(b * Sz + q0 + ty * 4 + i)) * Dz + h * DHz + tx * 8;
        float4 r0 = { o[i][0]*inv, o[i][1]*inv, o[i][2]*inv, o[i][3]*inv };
        float4 r1 = { o[i][4]*inv, o[i][5]*inv, o[i][6]*inv, o[i][7]*inv };
        *(float4*)&O[base]     = r0;
        *(float4*)&O[base + 4] = r1;
    }
}

// ---------------------------------------------------------------------------
// LayerNorm over last dim (2048), one CTA per row
// ---------------------------------------------------------------------------
__global__ __launch_bounds__(256) void ln_kernel(
    const float* __restrict__ X, const float* __restrict__ gamma,
    const float* __restrict__ beta, float* __restrict__ Y)
{
    const int row = blockIdx.x;
    const int tid = threadIdx.x;
    const float* x = X + (long)row * Dz;

    float v[8], s = 0.f, s2 = 0.f;
#pragma unroll
    for (int r = 0; r < 8; r++) {
        float t = x[r * 256 + tid];
        v[r] = t; s += t; s2 += t * t;
    }
#pragma unroll
    for (int d = 16; d >= 1; d >>= 1) {
        s  += __shfl_xor_sync(0xffffffffu, s,  d);
        s2 += __shfl_xor_sync(0xffffffffu, s2, d);
    }
    __shared__ float rs[8], rs2[8];
    __shared__ float s_mean, s_rstd;
    int wid = tid >> 5, lane = tid & 31;
    if (lane == 0) { rs[wid] = s; rs2[wid] = s2; }
    __syncthreads();
    if (tid == 0) {
        float S = 0.f, S2 = 0.f;
        for (int w = 0; w < 8; w++) { S += rs[w]; S2 += rs2[w]; }
        float mu = S * (1.f / 2048.f);
        float var = S2 * (1.f / 2048.f) - mu * mu;
        s_mean = mu;
        s_rstd = rsqrtf(var + 1e-5f);
    }
    __syncthreads();
    float mu = s_mean, rstd = s_rstd;
    float* y = Y + (long)row * Dz;
#pragma unroll
    for (int r = 0; r < 8; r++) {
        int c = r * 256 + tid;
        y[c] = (v[r] - mu) * rstd * gamma[c] + beta[c];
    }
}

// ---------------------------------------------------------------------------
extern "C" void kernel_launch(void* const* d_in, const int* in_sizes, int n_in,
                              void* d_out, int out_size)
{
    const float* q_input  = (const float*)d_in[0];
    const float* kv_input = (const float*)d_in[1];
    const int*   mask     = (const int*)d_in[2];
    const float* Wq = (const float*)d_in[3];
    const float* Wk = (const float*)d_in[4];
    const float* Wv = (const float*)d_in[5];
    const float* Wo = (const float*)d_in[6];
    const float* ln_gamma = (const float*)d_in[7];
    const float* ln_beta  = (const float*)d_in[8];
    const float* rope_cos = (const float*)d_in[9];
    const float* rope_sin = (const float*)d_in[10];
    float* out = (float*)d_out;

    float *pQ, *pK, *pV, *pA, *pR;
    __nv_bfloat16 *pih, *pil, *pwh, *pwl;
    cudaGetSymbolAddress((void**)&pQ, g_Q);
    cudaGetSymbolAddress((void**)&pK, g_K);
    cudaGetSymbolAddress((void**)&pV, g_V);
    cudaGetSymbolAddress((void**)&pA, g_A);
    cudaGetSymbolAddress((void**)&pR, g_R);
    cudaGetSymbolAddress((void**)&pih, g_inhi);
    cudaGetSymbolAddress((void**)&pil, g_inlo);
    cudaGetSymbolAddress((void**)&pwh, g_wthi);
    cudaGetSymbolAddress((void**)&pwl, g_wtlo);

    cudaFuncSetAttribute(flash_kernel,
                         cudaFuncAttributeMaxDynamicSharedMemorySize, FL_SMEM);

    const int M = Bz * Sz;                       // 8192
    dim3 wgrid(16, 64);                          // (N/128, M/128)
    dim3 tgrid(64, 64);                          // weight transpose blocks
    dim3 tblk(32, 8);
    const int split_blocks = (int)(TOT / 4 / 256);

    // ---- Q projection
    split_f32<<<split_blocks, 256>>>((const float4*)q_input, pih, pil);
    split_wT<<<tgrid, tblk>>>(Wq, pwh, pwl);
    wgemm<<<wgrid, 256>>>(pih, pil, pwh, pwl, nullptr, pQ);

    // ---- K / V projections (shared kv_input split)
    split_f32<<<split_blocks, 256>>>((const float4*)kv_input, pih, pil);
    split_wT<<<tgrid, tblk>>>(Wk, pwh, pwl);
    wgemm<<<wgrid, 256>>>(pih, pil, pwh, pwl, nullptr, pK);
    split_wT<<<tgrid, tblk>>>(Wv, pwh, pwl);
    wgemm<<<wgrid, 256>>>(pih, pil, pwh, pwl, nullptr, pV);

    // ---- RoPE
    int rope_threads = Bz * Sz * NHz * 64;
    rope_kernel<<<rope_threads / 256, 256>>>(pQ, rope_cos, rope_sin);
    rope_kernel<<<rope_threads / 256, 256>>>(pK, rope_cos, rope_sin);

    // ---- attention
    flash_kernel<<<Bz * NHz * (Sz / 64), 256, FL_SMEM>>>(pQ, pK, pV, mask, pA);

    // ---- output projection + residual
    split_f32<<<split_blocks, 256>>>((const float4*)pA, pih, pil);
    split_wT<<<tgrid, tblk>>>(Wo, pwh, pwl);
    wgemm<<<wgrid, 256>>>(pih, pil, pwh, pwl, q_input, pR);

    // ---- LayerNorm
    ln_kernel<<<M, 256>>>(pR, ln_gamma, ln_beta, out);
}